// round 3
// baseline (speedup 1.0000x reference)
#include <cuda_runtime.h>
#include <math.h>

#define B_  64
#define T_  256
#define D_  384
#define H_  6
#define HS_ 64
#define L_  6
#define V_  65
#define FF_ 1536
#define M_  (B_*T_)   // 16384 tokens

// ---------------- scratch (device globals; no allocation allowed) ----------------
__device__ float g_x[M_*D_];          // residual stream
__device__ float g_y[M_*D_];          // layernorm output
__device__ float g_qkv[M_*3*D_];      // fused qkv
__device__ float g_o[M_*D_];          // attention output (head-concat)
__device__ float g_h1[M_*FF_];        // FFN hidden
__device__ float g_wqkv[L_*D_*3*D_];  // repacked qkv weights [L][D][3D]
__device__ float g_logits[M_*V_];     // fallback logits buffer
__device__ float g_losspart[2048];    // per-block loss partials

// ---------------- repack Wq/Wk/Wv [L,H,D,HS] -> [L, D, 3D] ----------------
__global__ void repack_k(const float* __restrict__ Wq, const float* __restrict__ Wk,
                         const float* __restrict__ Wv, float* __restrict__ wqkv) {
    long i = (long)blockIdx.x * blockDim.x + threadIdx.x;
    const long total = (long)L_ * D_ * 3 * D_;
    if (i >= total) return;
    int c = (int)(i % (3 * D_));
    long tmp = i / (3 * D_);
    int d = (int)(tmp % D_);
    int l = (int)(tmp / D_);
    const float* W; int cc;
    if (c < D_)          { W = Wq; cc = c; }
    else if (c < 2 * D_) { W = Wk; cc = c - D_; }
    else                 { W = Wv; cc = c - 2 * D_; }
    int h = cc / HS_, e = cc % HS_;
    wqkv[i] = W[(((long)l * H_ + h) * D_ + d) * HS_ + e];
}

// ---------------- embedding ----------------
__global__ void embed_k(const int* __restrict__ idx, const float* __restrict__ tok,
                        const float* __restrict__ pos, float* __restrict__ x) {
    int i = blockIdx.x * blockDim.x + threadIdx.x;
    if (i >= M_ * D_) return;
    int d = i % D_;
    int r = i / D_;
    int t = r % T_;
    x[i] = tok[(long)idx[r] * D_ + d] + pos[(long)t * D_ + d];
}

// ---------------- layernorm (block per row, 128 threads) ----------------
__global__ void ln_k(const float* __restrict__ x, float* __restrict__ y,
                     const float* __restrict__ g, const float* __restrict__ b) {
    int row = blockIdx.x;
    const float* xr = x + (long)row * D_;
    float s = 0.f, s2 = 0.f;
    for (int d = threadIdx.x; d < D_; d += 128) { float v = xr[d]; s += v; s2 += v * v; }
    #pragma unroll
    for (int o = 16; o; o >>= 1) {
        s  += __shfl_xor_sync(0xffffffffu, s,  o);
        s2 += __shfl_xor_sync(0xffffffffu, s2, o);
    }
    __shared__ float ss[4], ss2[4];
    int w = threadIdx.x >> 5;
    if ((threadIdx.x & 31) == 0) { ss[w] = s; ss2[w] = s2; }
    __syncthreads();
    s  = ss[0] + ss[1] + ss[2] + ss[3];
    s2 = ss2[0] + ss2[1] + ss2[2] + ss2[3];
    float mean = s * (1.f / D_);
    float var  = s2 * (1.f / D_) - mean * mean;
    float inv  = rsqrtf(var + 1e-5f);
    float* yr = y + (long)row * D_;
    for (int d = threadIdx.x; d < D_; d += 128)
        yr[d] = (xr[d] - mean) * inv * g[d] + b[d];
}

// ---------------- generic fp32 GEMM: C = [Cin +] A@Bw [+ bias] [relu] ----------------
// A:[M_,K] row-major, Bw:[K,N] row-major, C:[M_,N]. Tile 128x128x8, 256 thr, 8x8 micro.
// M_ % 128 == 0 and K % 8 == 0 always hold here; only N needs guards (N=65 case).
// NOTE: vectorized B loads only when N % 4 == 0 (row stride 16B-aligned); the
// N=65 head GEMM takes the scalar path (misaligned float4 otherwise).
__global__ void gemm_k(const float* __restrict__ A, const float* __restrict__ Bw,
                       const float* __restrict__ bias, const float* __restrict__ Cin,
                       float* __restrict__ C, int N, int K, int relu) {
    __shared__ float As[8][128];
    __shared__ float Bs[8][128];
    int tid = threadIdx.x;
    int m0 = blockIdx.y * 128, n0 = blockIdx.x * 128;
    int arow = tid >> 1, ac4 = (tid & 1) * 4;
    int brow = tid >> 5, bcol = (tid & 31) * 4;
    int ty = tid >> 4, tx = tid & 15;

    float acc[8][8];
    #pragma unroll
    for (int i = 0; i < 8; i++)
        #pragma unroll
        for (int j = 0; j < 8; j++) acc[i][j] = 0.f;

    const float* Aptr = A + (long)(m0 + arow) * K + ac4;

    for (int kt = 0; kt < K; kt += 8) {
        float4 av = *(const float4*)(Aptr + kt);
        As[ac4 + 0][arow] = av.x; As[ac4 + 1][arow] = av.y;
        As[ac4 + 2][arow] = av.z; As[ac4 + 3][arow] = av.w;

        int col = n0 + bcol;
        float4 bv;
        const float* bp = Bw + (long)(kt + brow) * N;
        if (((N & 3) == 0) && (col + 3 < N)) {
            bv = *(const float4*)(bp + col);
        } else {
            bv.x = (col + 0 < N) ? bp[col + 0] : 0.f;
            bv.y = (col + 1 < N) ? bp[col + 1] : 0.f;
            bv.z = (col + 2 < N) ? bp[col + 2] : 0.f;
            bv.w = (col + 3 < N) ? bp[col + 3] : 0.f;
        }
        *(float4*)&Bs[brow][bcol] = bv;
        __syncthreads();

        #pragma unroll
        for (int kk = 0; kk < 8; kk++) {
            float a[8], bb[8];
            *(float4*)&a[0]  = *(const float4*)&As[kk][ty * 8];
            *(float4*)&a[4]  = *(const float4*)&As[kk][ty * 8 + 4];
            *(float4*)&bb[0] = *(const float4*)&Bs[kk][tx * 8];
            *(float4*)&bb[4] = *(const float4*)&Bs[kk][tx * 8 + 4];
            #pragma unroll
            for (int i = 0; i < 8; i++)
                #pragma unroll
                for (int j = 0; j < 8; j++) acc[i][j] += a[i] * bb[j];
        }
        __syncthreads();
    }

    #pragma unroll
    for (int i = 0; i < 8; i++) {
        long row = m0 + ty * 8 + i;
        float* crow = C + row * (long)N;
        const float* cir = Cin ? (Cin + row * (long)N) : (const float*)0;
        #pragma unroll
        for (int j = 0; j < 8; j++) {
            int col = n0 + tx * 8 + j;
            if (col < N) {
                float v = acc[i][j];
                if (bias) v += bias[col];
                if (cir)  v += cir[col];
                if (relu) v = fmaxf(v, 0.f);
                crow[col] = v;
            }
        }
    }
}

// ---------------- fused causal attention: block per (b,h), thread per query row ----------------
__global__ void attn_k(const float* __restrict__ qkv, float* __restrict__ o) {
    extern __shared__ float sm[];
    float* Ks = sm;              // [T_][HS_]
    float* Vs = sm + T_ * HS_;   // [T_][HS_]
    int bh = blockIdx.x;
    int b = bh / H_, h = bh % H_;
    int t = threadIdx.x;         // 256 threads = T_ query rows
    const long base = (long)b * T_ * 3 * D_;

    // cooperative load of K and V tiles for this (b,h)
    for (int i = t; i < T_ * (HS_ / 4); i += blockDim.x) {
        int row = i / (HS_ / 4);
        int c4  = i % (HS_ / 4);
        const float* krow = qkv + base + (long)row * 3 * D_ + D_     + h * HS_;
        const float* vrow = qkv + base + (long)row * 3 * D_ + 2 * D_ + h * HS_;
        ((float4*)Ks)[i] = ((const float4*)krow)[c4];
        ((float4*)Vs)[i] = ((const float4*)vrow)[c4];
    }
    __syncthreads();

    float4 qv[16];
    {
        const float4* qp = (const float4*)(qkv + base + (long)t * 3 * D_ + h * HS_);
        #pragma unroll
        for (int j = 0; j < 16; j++) qv[j] = qp[j];
    }
    const float scale = 0.05103103630798288f;  // 384^-0.5

    // pass 1: running max + denominator (causal: tk <= t)
    float m = -1e30f, lsum = 0.f;
    for (int tk = 0; tk < T_; tk++) {
        const float4* kr = (const float4*)(Ks + tk * HS_);
        float s = 0.f;
        #pragma unroll
        for (int j = 0; j < 16; j++) {
            float4 k4 = kr[j];
            s += qv[j].x * k4.x + qv[j].y * k4.y + qv[j].z * k4.z + qv[j].w * k4.w;
        }
        s *= scale;
        if (tk <= t) {
            float mn = fmaxf(m, s);
            lsum = lsum * __expf(m - mn) + __expf(s - mn);
            m = mn;
        }
    }

    // pass 2: recompute scores, accumulate P @ V
    float acc[HS_];
    #pragma unroll
    for (int e = 0; e < HS_; e++) acc[e] = 0.f;
    for (int tk = 0; tk <= t; tk++) {
        const float4* kr = (const float4*)(Ks + tk * HS_);
        float s = 0.f;
        #pragma unroll
        for (int j = 0; j < 16; j++) {
            float4 k4 = kr[j];
            s += qv[j].x * k4.x + qv[j].y * k4.y + qv[j].z * k4.z + qv[j].w * k4.w;
        }
        float p = __expf(s * scale - m);
        const float* vr = Vs + tk * HS_;
        #pragma unroll
        for (int e = 0; e < HS_; e++) acc[e] += p * vr[e];
    }
    float rl = 1.f / lsum;
    float* orow = o + ((long)b * T_ + t) * D_ + h * HS_;
    #pragma unroll
    for (int e = 0; e < HS_; e++) orow[e] = acc[e] * rl;
}

// ---------------- loss: warp per row, logsumexp ----------------
__global__ void loss_k(const float* __restrict__ logits, const int* __restrict__ targets,
                       float* __restrict__ part) {
    int gwarp = (blockIdx.x * blockDim.x + threadIdx.x) >> 5;   // 2048 blk * 8 warps = M_
    int lane = threadIdx.x & 31;
    const float* lr = logits + (long)gwarp * V_;
    float mx = -1e30f;
    for (int c = lane; c < V_; c += 32) mx = fmaxf(mx, lr[c]);
    #pragma unroll
    for (int o = 16; o; o >>= 1) mx = fmaxf(mx, __shfl_xor_sync(0xffffffffu, mx, o));
    float se = 0.f;
    for (int c = lane; c < V_; c += 32) se += expf(lr[c] - mx);
    #pragma unroll
    for (int o = 16; o; o >>= 1) se += __shfl_xor_sync(0xffffffffu, se, o);
    float li = (mx + logf(se)) - lr[targets[gwarp]];
    __shared__ float ws[8];
    if (lane == 0) ws[threadIdx.x >> 5] = li;
    __syncthreads();
    if (threadIdx.x == 0) {
        float s = 0.f;
        #pragma unroll
        for (int i = 0; i < 8; i++) s += ws[i];
        part[blockIdx.x] = s;
    }
}

__global__ void finalize_k(float* out, long out_size, const float* __restrict__ part) {
    float v = 0.f;
    for (int i = threadIdx.x; i < 2048; i += 256) v += part[i];
    #pragma unroll
    for (int o = 16; o; o >>= 1) v += __shfl_xor_sync(0xffffffffu, v, o);
    __shared__ float sm[8];
    if ((threadIdx.x & 31) == 0) sm[threadIdx.x >> 5] = v;
    __syncthreads();
    if (threadIdx.x == 0) {
        float s = 0.f;
        #pragma unroll
        for (int i = 0; i < 8; i++) s += sm[i];
        float loss = s / (float)M_;
        const long btv = (long)M_ * V_;
        if (out_size > btv)       out[btv] = loss;
        else if (out_size == 1)   out[0]   = loss;
    }
}

// ---------------- driver ----------------
extern "C" void kernel_launch(void* const* d_in, const int* in_sizes, int n_in,
                              void* d_out, int out_size) {
    const int*   idx     = (const int*)d_in[0];
    const int*   targets = (const int*)d_in[1];
    const float* tok     = (const float*)d_in[2];
    const float* pos     = (const float*)d_in[3];
    const float* Wq      = (const float*)d_in[4];
    const float* Wk      = (const float*)d_in[5];
    const float* Wv      = (const float*)d_in[6];
    const float* Wproj   = (const float*)d_in[7];
    const float* bproj   = (const float*)d_in[8];
    const float* W1      = (const float*)d_in[9];
    const float* b1      = (const float*)d_in[10];
    const float* W2      = (const float*)d_in[11];
    const float* b2      = (const float*)d_in[12];
    const float* ln1g    = (const float*)d_in[13];
    const float* ln1b    = (const float*)d_in[14];
    const float* lnfg    = (const float*)d_in[15];
    const float* lnfb    = (const float*)d_in[16];
    const float* Whead   = (const float*)d_in[17];
    const float* bhead   = (const float*)d_in[18];
    float* out = (float*)d_out;

    float *x, *y, *qkv, *o, *h1, *wqkv, *lgts, *part;
    cudaGetSymbolAddress((void**)&x,    g_x);
    cudaGetSymbolAddress((void**)&y,    g_y);
    cudaGetSymbolAddress((void**)&qkv,  g_qkv);
    cudaGetSymbolAddress((void**)&o,    g_o);
    cudaGetSymbolAddress((void**)&h1,   g_h1);
    cudaGetSymbolAddress((void**)&wqkv, g_wqkv);
    cudaGetSymbolAddress((void**)&lgts, g_logits);
    cudaGetSymbolAddress((void**)&part, g_losspart);

    const int attn_smem = 2 * T_ * HS_ * 4;   // 128 KB
    cudaFuncSetAttribute(attn_k, cudaFuncAttributeMaxDynamicSharedMemorySize, attn_smem);

    const long btv = (long)M_ * V_;
    float* logits = ((long)out_size >= btv) ? out : lgts;

    {
        long total = (long)L_ * D_ * 3 * D_;
        repack_k<<<(int)((total + 255) / 256), 256>>>(Wq, Wk, Wv, wqkv);
    }
    embed_k<<<(M_ * D_ + 255) / 256, 256>>>(idx, tok, pos, x);

    for (int l = 0; l < L_; l++) {
        ln_k<<<M_, 128>>>(x, y, ln1g + (long)l * D_, ln1b + (long)l * D_);
        { dim3 g(9, 128);  gemm_k<<<g, 256>>>(y, wqkv + (long)l * D_ * 3 * D_, (const float*)0, (const float*)0, qkv, 3 * D_, D_, 0); }
        attn_k<<<B_ * H_, 256, attn_smem>>>(qkv, o);
        { dim3 g(3, 128);  gemm_k<<<g, 256>>>(o, Wproj + (long)l * D_ * D_, bproj + (long)l * D_, x, x, D_, D_, 0); }
        ln_k<<<M_, 128>>>(x, y, ln1g + (long)l * D_, ln1b + (long)l * D_);   // faithful: reuses ln1
        { dim3 g(12, 128); gemm_k<<<g, 256>>>(y, W1 + (long)l * D_ * FF_, b1 + (long)l * FF_, (const float*)0, h1, FF_, D_, 1); }
        { dim3 g(3, 128);  gemm_k<<<g, 256>>>(h1, W2 + (long)l * FF_ * D_, b2 + (long)l * D_, x, x, D_, FF_, 0); }
    }

    ln_k<<<M_, 128>>>(x, y, lnfg, lnfb);
    { dim3 g(1, 128); gemm_k<<<g, 256>>>(y, Whead, bhead, (const float*)0, logits, V_, D_, 0); }
    loss_k<<<2048, 256>>>(logits, targets, part);
    finalize_k<<<1, 256>>>(out, (long)out_size, part);
}

// round 5
// speedup vs baseline: 1.6565x; 1.6565x over previous
#include <cuda_runtime.h>
#include <math.h>

#define B_  64
#define T_  256
#define D_  384
#define H_  6
#define HS_ 64
#define L_  6
#define V_  65
#define FF_ 1536
#define M_  (B_*T_)   // 16384 tokens

// ---------------- scratch (device globals; no allocation allowed) ----------------
__device__ float g_x[M_*D_];          // residual stream
__device__ float g_y[M_*D_];          // layernorm output
__device__ float g_qkv[M_*3*D_];      // fused qkv
__device__ float g_o[M_*D_];          // attention output (head-concat)
__device__ float g_h1[M_*FF_];        // FFN hidden
__device__ float g_wqkv[L_*D_*3*D_];  // repacked qkv weights [L][D][3D]
__device__ float g_logits[M_*V_];     // fallback logits buffer
__device__ float g_losspart[2048];    // per-block loss partials

// ---------------- f32x2 helpers (sm_103a packed fp32 FMA) ----------------
__device__ __forceinline__ unsigned long long rep2(float x) {
    unsigned long long r;
    asm("mov.b64 %0, {%1, %1};" : "=l"(r) : "f"(x));
    return r;
}
__device__ __forceinline__ void ffma2(unsigned long long &d, unsigned long long a, unsigned long long b) {
    asm("fma.rn.f32x2 %0, %1, %2, %0;" : "+l"(d) : "l"(a), "l"(b));
}
__device__ __forceinline__ float2 unpk2(unsigned long long v) {
    float2 r;
    asm("mov.b64 {%0, %1}, %2;" : "=f"(r.x), "=f"(r.y) : "l"(v));
    return r;
}

// ---------------- repack Wq/Wk/Wv [L,H,D,HS] -> [L, D, 3D] ----------------
__global__ void repack_k(const float* __restrict__ Wq, const float* __restrict__ Wk,
                         const float* __restrict__ Wv, float* __restrict__ wqkv) {
    long i = (long)blockIdx.x * blockDim.x + threadIdx.x;
    const long total = (long)L_ * D_ * 3 * D_;
    if (i >= total) return;
    int c = (int)(i % (3 * D_));
    long tmp = i / (3 * D_);
    int d = (int)(tmp % D_);
    int l = (int)(tmp / D_);
    const float* W; int cc;
    if (c < D_)          { W = Wq; cc = c; }
    else if (c < 2 * D_) { W = Wk; cc = c - D_; }
    else                 { W = Wv; cc = c - 2 * D_; }
    int h = cc / HS_, e = cc % HS_;
    wqkv[i] = W[(((long)l * H_ + h) * D_ + d) * HS_ + e];
}

// ---------------- embedding ----------------
__global__ void embed_k(const int* __restrict__ idx, const float* __restrict__ tok,
                        const float* __restrict__ pos, float* __restrict__ x) {
    int i = blockIdx.x * blockDim.x + threadIdx.x;
    if (i >= M_ * D_) return;
    int d = i % D_;
    int r = i / D_;
    int t = r % T_;
    x[i] = tok[(long)idx[r] * D_ + d] + pos[(long)t * D_ + d];
}

// ---------------- layernorm (block per row, 128 threads) ----------------
__global__ void ln_k(const float* __restrict__ x, float* __restrict__ y,
                     const float* __restrict__ g, const float* __restrict__ b) {
    int row = blockIdx.x;
    const float* xr = x + (long)row * D_;
    float s = 0.f, s2 = 0.f;
    for (int d = threadIdx.x; d < D_; d += 128) { float v = xr[d]; s += v; s2 += v * v; }
    #pragma unroll
    for (int o = 16; o; o >>= 1) {
        s  += __shfl_xor_sync(0xffffffffu, s,  o);
        s2 += __shfl_xor_sync(0xffffffffu, s2, o);
    }
    __shared__ float ss[4], ss2[4];
    int w = threadIdx.x >> 5;
    if ((threadIdx.x & 31) == 0) { ss[w] = s; ss2[w] = s2; }
    __syncthreads();
    s  = ss[0] + ss[1] + ss[2] + ss[3];
    s2 = ss2[0] + ss2[1] + ss2[2] + ss2[3];
    float mean = s * (1.f / D_);
    float var  = s2 * (1.f / D_) - mean * mean;
    float inv  = rsqrtf(var + 1e-5f);
    float* yr = y + (long)row * D_;
    for (int d = threadIdx.x; d < D_; d += 128)
        yr[d] = (xr[d] - mean) * inv * g[d] + b[d];
}

// ---------------- fast fp32 GEMM (N % 128 == 0, K % 16 == 0) ----------------
// C = [Cin +] A@Bw [+ bias] [relu]. Tile 128x128x16, double-buffered smem,
// 256 threads, 8x8 micro-tile computed as 4 row-pairs with fma.rn.f32x2.
__global__ void __launch_bounds__(256, 2)
gemm128_k(const float* __restrict__ A, const float* __restrict__ Bw,
          const float* __restrict__ bias, const float* __restrict__ Cin,
          float* __restrict__ C, int N, int K, int relu) {
    __shared__ float As[2][16][128];   // [buf][k][m]
    __shared__ float Bs[2][16][128];   // [buf][k][n]
    int tid = threadIdx.x;
    int m0 = blockIdx.y * 128, n0 = blockIdx.x * 128;
    int arow = tid >> 1,  ac = (tid & 1) * 8;    // A: 128 rows x 16 k, 8 floats/thread
    int brow = tid >> 4,  bc = (tid & 15) * 8;   // B: 16 k x 128 cols, 8 floats/thread
    int ty = tid >> 4,    tx = tid & 15;

    unsigned long long acc[4][8];   // [row-pair][col], each holds (row2p, row2p+1)
    #pragma unroll
    for (int p = 0; p < 4; p++)
        #pragma unroll
        for (int j = 0; j < 8; j++) acc[p][j] = 0ull;

    const float* Ap = A + (long)(m0 + arow) * K + ac;
    const float* Bp = Bw + (long)brow * N + n0 + bc;
    const long  bstep = (long)16 * N;
    const int nt = K >> 4;

    // preload tile 0
    float4 pa0 = *(const float4*)(Ap);
    float4 pa1 = *(const float4*)(Ap + 4);
    float4 pb0 = *(const float4*)(Bp);
    float4 pb1 = *(const float4*)(Bp + 4);
    {
        As[0][ac+0][arow]=pa0.x; As[0][ac+1][arow]=pa0.y; As[0][ac+2][arow]=pa0.z; As[0][ac+3][arow]=pa0.w;
        As[0][ac+4][arow]=pa1.x; As[0][ac+5][arow]=pa1.y; As[0][ac+6][arow]=pa1.z; As[0][ac+7][arow]=pa1.w;
        *(float4*)&Bs[0][brow][bc]   = pb0;
        *(float4*)&Bs[0][brow][bc+4] = pb1;
    }
    __syncthreads();

    for (int it = 0; it < nt; it++) {
        int cur = it & 1;
        bool more = (it + 1) < nt;
        if (more) {
            const float* ap = Ap + (it + 1) * 16;
            const float* bp = Bp + (it + 1) * bstep;
            pa0 = *(const float4*)(ap);
            pa1 = *(const float4*)(ap + 4);
            pb0 = *(const float4*)(bp);
            pb1 = *(const float4*)(bp + 4);
        }

        #pragma unroll
        for (int kk = 0; kk < 16; kk++) {
            const unsigned long long* ar = (const unsigned long long*)&As[cur][kk][ty * 8];
            unsigned long long a0 = ar[0], a1 = ar[1], a2 = ar[2], a3 = ar[3];
            float4 bf0 = *(const float4*)&Bs[cur][kk][tx * 8];
            float4 bf1 = *(const float4*)&Bs[cur][kk][tx * 8 + 4];
            unsigned long long b2[8];
            b2[0] = rep2(bf0.x); b2[1] = rep2(bf0.y); b2[2] = rep2(bf0.z); b2[3] = rep2(bf0.w);
            b2[4] = rep2(bf1.x); b2[5] = rep2(bf1.y); b2[6] = rep2(bf1.z); b2[7] = rep2(bf1.w);
            #pragma unroll
            for (int j = 0; j < 8; j++) {
                ffma2(acc[0][j], a0, b2[j]);
                ffma2(acc[1][j], a1, b2[j]);
                ffma2(acc[2][j], a2, b2[j]);
                ffma2(acc[3][j], a3, b2[j]);
            }
        }

        if (more) {
            int nxt = cur ^ 1;
            As[nxt][ac+0][arow]=pa0.x; As[nxt][ac+1][arow]=pa0.y; As[nxt][ac+2][arow]=pa0.z; As[nxt][ac+3][arow]=pa0.w;
            As[nxt][ac+4][arow]=pa1.x; As[nxt][ac+5][arow]=pa1.y; As[nxt][ac+6][arow]=pa1.z; As[nxt][ac+7][arow]=pa1.w;
            *(float4*)&Bs[nxt][brow][bc]   = pb0;
            *(float4*)&Bs[nxt][brow][bc+4] = pb1;
        }
        __syncthreads();
    }

    // epilogue: rows m0 + ty*8 + {0..7}, cols n0 + tx*8 + {0..7}
    #pragma unroll
    for (int p = 0; p < 4; p++) {
        float r0v[8], r1v[8];
        #pragma unroll
        for (int j = 0; j < 8; j++) {
            float2 v = unpk2(acc[p][j]);
            r0v[j] = v.x; r1v[j] = v.y;
        }
        #pragma unroll
        for (int half = 0; half < 2; half++) {
            float* rv = half ? r1v : r0v;
            long row = m0 + ty * 8 + 2 * p + half;
            int coln = n0 + tx * 8;
            float* crow = C + row * (long)N + coln;
            if (bias) {
                #pragma unroll
                for (int j = 0; j < 8; j++) rv[j] += bias[coln + j];
            }
            if (Cin) {
                const float* cir = Cin + row * (long)N + coln;
                float4 c0 = *(const float4*)(cir);
                float4 c1 = *(const float4*)(cir + 4);
                rv[0]+=c0.x; rv[1]+=c0.y; rv[2]+=c0.z; rv[3]+=c0.w;
                rv[4]+=c1.x; rv[5]+=c1.y; rv[6]+=c1.z; rv[7]+=c1.w;
            }
            if (relu) {
                #pragma unroll
                for (int j = 0; j < 8; j++) rv[j] = fmaxf(rv[j], 0.f);
            }
            float4 o0 = make_float4(rv[0], rv[1], rv[2], rv[3]);
            float4 o1 = make_float4(rv[4], rv[5], rv[6], rv[7]);
            *(float4*)(crow)     = o0;
            *(float4*)(crow + 4) = o1;
        }
    }
}

// ---------------- small-N GEMM (head, N=65): safe scalar-B path ----------------
__global__ void gemm_k(const float* __restrict__ A, const float* __restrict__ Bw,
                       const float* __restrict__ bias, const float* __restrict__ Cin,
                       float* __restrict__ C, int N, int K, int relu) {
    __shared__ float As[8][128];
    __shared__ float Bs[8][128];
    int tid = threadIdx.x;
    int m0 = blockIdx.y * 128, n0 = blockIdx.x * 128;
    int arow = tid >> 1, ac4 = (tid & 1) * 4;
    int brow = tid >> 5, bcol = (tid & 31) * 4;
    int ty = tid >> 4, tx = tid & 15;

    float acc[8][8];
    #pragma unroll
    for (int i = 0; i < 8; i++)
        #pragma unroll
        for (int j = 0; j < 8; j++) acc[i][j] = 0.f;

    const float* Aptr = A + (long)(m0 + arow) * K + ac4;

    for (int kt = 0; kt < K; kt += 8) {
        float4 av = *(const float4*)(Aptr + kt);
        As[ac4 + 0][arow] = av.x; As[ac4 + 1][arow] = av.y;
        As[ac4 + 2][arow] = av.z; As[ac4 + 3][arow] = av.w;

        int col = n0 + bcol;
        float4 bv;
        const float* bp = Bw + (long)(kt + brow) * N;
        bv.x = (col + 0 < N) ? bp[col + 0] : 0.f;
        bv.y = (col + 1 < N) ? bp[col + 1] : 0.f;
        bv.z = (col + 2 < N) ? bp[col + 2] : 0.f;
        bv.w = (col + 3 < N) ? bp[col + 3] : 0.f;
        *(float4*)&Bs[brow][bcol] = bv;
        __syncthreads();

        #pragma unroll
        for (int kk = 0; kk < 8; kk++) {
            float a[8], bb[8];
            *(float4*)&a[0]  = *(const float4*)&As[kk][ty * 8];
            *(float4*)&a[4]  = *(const float4*)&As[kk][ty * 8 + 4];
            *(float4*)&bb[0] = *(const float4*)&Bs[kk][tx * 8];
            *(float4*)&bb[4] = *(const float4*)&Bs[kk][tx * 8 + 4];
            #pragma unroll
            for (int i = 0; i < 8; i++)
                #pragma unroll
                for (int j = 0; j < 8; j++) acc[i][j] += a[i] * bb[j];
        }
        __syncthreads();
    }

    #pragma unroll
    for (int i = 0; i < 8; i++) {
        long row = m0 + ty * 8 + i;
        float* crow = C + row * (long)N;
        const float* cir = Cin ? (Cin + row * (long)N) : (const float*)0;
        #pragma unroll
        for (int j = 0; j < 8; j++) {
            int col = n0 + tx * 8 + j;
            if (col < N) {
                float v = acc[i][j];
                if (bias) v += bias[col];
                if (cir)  v += cir[col];
                if (relu) v = fmaxf(v, 0.f);
                crow[col] = v;
            }
        }
    }
}

// ---------------- fused causal attention: block per (b,h), thread per query row ----------------
// single-pass online softmax with branch-guarded rescale
__global__ void attn_k(const float* __restrict__ qkv, float* __restrict__ o) {
    extern __shared__ float sm[];
    float* Ks = sm;              // [T_][HS_]
    float* Vs = sm + T_ * HS_;   // [T_][HS_]
    int bh = blockIdx.x;
    int b = bh / H_, h = bh % H_;
    int t = threadIdx.x;         // 256 threads = T_ query rows
    const long base = (long)b * T_ * 3 * D_;

    for (int i = t; i < T_ * (HS_ / 4); i += blockDim.x) {
        int row = i / (HS_ / 4);
        int c4  = i % (HS_ / 4);
        const float* krow = qkv + base + (long)row * 3 * D_ + D_     + h * HS_;
        const float* vrow = qkv + base + (long)row * 3 * D_ + 2 * D_ + h * HS_;
        ((float4*)Ks)[i] = ((const float4*)krow)[c4];
        ((float4*)Vs)[i] = ((const float4*)vrow)[c4];
    }
    __syncthreads();

    float4 qv[16];
    {
        const float4* qp = (const float4*)(qkv + base + (long)t * 3 * D_ + h * HS_);
        #pragma unroll
        for (int j = 0; j < 16; j++) qv[j] = qp[j];
    }
    const float scale = 0.05103103630798288f;  // 384^-0.5

    float m = -1e30f, lsum = 0.f;
    float acc[HS_];
    #pragma unroll
    for (int e = 0; e < HS_; e++) acc[e] = 0.f;

    for (int tk = 0; tk <= t; tk++) {
        const float4* kr = (const float4*)(Ks + tk * HS_);
        float s = 0.f;
        #pragma unroll
        for (int j = 0; j < 16; j++) {
            float4 k4 = kr[j];
            s += qv[j].x * k4.x + qv[j].y * k4.y + qv[j].z * k4.z + qv[j].w * k4.w;
        }
        s *= scale;
        const float* vr = Vs + tk * HS_;
        if (s > m) {
            float c = __expf(m - s);    // first iter: exp(-inf) = 0
            lsum = lsum * c + 1.f;
            #pragma unroll
            for (int e = 0; e < HS_; e++) acc[e] = acc[e] * c + vr[e];
            m = s;
        } else {
            float p = __expf(s - m);
            lsum += p;
            #pragma unroll
            for (int e = 0; e < HS_; e++) acc[e] += p * vr[e];
        }
    }
    float rl = 1.f / lsum;
    float* orow = o + ((long)b * T_ + t) * D_ + h * HS_;
    #pragma unroll
    for (int e = 0; e < HS_; e++) orow[e] = acc[e] * rl;
}

// ---------------- loss: warp per row, logsumexp ----------------
__global__ void loss_k(const float* __restrict__ logits, const int* __restrict__ targets,
                       float* __restrict__ part) {
    int gwarp = (blockIdx.x * blockDim.x + threadIdx.x) >> 5;   // 2048 blk * 8 warps = M_
    int lane = threadIdx.x & 31;
    const float* lr = logits + (long)gwarp * V_;
    float mx = -1e30f;
    for (int c = lane; c < V_; c += 32) mx = fmaxf(mx, lr[c]);
    #pragma unroll
    for (int o = 16; o; o >>= 1) mx = fmaxf(mx, __shfl_xor_sync(0xffffffffu, mx, o));
    float se = 0.f;
    for (int c = lane; c < V_; c += 32) se += expf(lr[c] - mx);
    #pragma unroll
    for (int o = 16; o; o >>= 1) se += __shfl_xor_sync(0xffffffffu, se, o);
    float li = (mx + logf(se)) - lr[targets[gwarp]];
    __shared__ float ws[8];
    if (lane == 0) ws[threadIdx.x >> 5] = li;
    __syncthreads();
    if (threadIdx.x == 0) {
        float s = 0.f;
        #pragma unroll
        for (int i = 0; i < 8; i++) s += ws[i];
        part[blockIdx.x] = s;
    }
}

__global__ void finalize_k(float* out, long out_size, const float* __restrict__ part) {
    float v = 0.f;
    for (int i = threadIdx.x; i < 2048; i += 256) v += part[i];
    #pragma unroll
    for (int o = 16; o; o >>= 1) v += __shfl_xor_sync(0xffffffffu, v, o);
    __shared__ float sm[8];
    if ((threadIdx.x & 31) == 0) sm[threadIdx.x >> 5] = v;
    __syncthreads();
    if (threadIdx.x == 0) {
        float s = 0.f;
        #pragma unroll
        for (int i = 0; i < 8; i++) s += sm[i];
        float loss = s / (float)M_;
        const long btv = (long)M_ * V_;
        if (out_size > btv)       out[btv] = loss;
        else if (out_size == 1)   out[0]   = loss;
    }
}

// ---------------- driver ----------------
extern "C" void kernel_launch(void* const* d_in, const int* in_sizes, int n_in,
                              void* d_out, int out_size) {
    const int*   idx     = (const int*)d_in[0];
    const int*   targets = (const int*)d_in[1];
    const float* tok     = (const float*)d_in[2];
    const float* pos     = (const float*)d_in[3];
    const float* Wq      = (const float*)d_in[4];
    const float* Wk      = (const float*)d_in[5];
    const float* Wv      = (const float*)d_in[6];
    const float* Wproj   = (const float*)d_in[7];
    const float* bproj   = (const float*)d_in[8];
    const float* W1      = (const float*)d_in[9];
    const float* b1      = (const float*)d_in[10];
    const float* W2      = (const float*)d_in[11];
    const float* b2      = (const float*)d_in[12];
    const float* ln1g    = (const float*)d_in[13];
    const float* ln1b    = (const float*)d_in[14];
    const float* lnfg    = (const float*)d_in[15];
    const float* lnfb    = (const float*)d_in[16];
    const float* Whead   = (const float*)d_in[17];
    const float* bhead   = (const float*)d_in[18];
    float* out = (float*)d_out;

    float *x, *y, *qkv, *o, *h1, *wqkv, *lgts, *part;
    cudaGetSymbolAddress((void**)&x,    g_x);
    cudaGetSymbolAddress((void**)&y,    g_y);
    cudaGetSymbolAddress((void**)&qkv,  g_qkv);
    cudaGetSymbolAddress((void**)&o,    g_o);
    cudaGetSymbolAddress((void**)&h1,   g_h1);
    cudaGetSymbolAddress((void**)&wqkv, g_wqkv);
    cudaGetSymbolAddress((void**)&lgts, g_logits);
    cudaGetSymbolAddress((void**)&part, g_losspart);

    const int attn_smem = 2 * T_ * HS_ * 4;   // 128 KB
    cudaFuncSetAttribute(attn_k, cudaFuncAttributeMaxDynamicSharedMemorySize, attn_smem);

    const long btv = (long)M_ * V_;
    float* logits = ((long)out_size >= btv) ? out : lgts;

    {
        long total = (long)L_ * D_ * 3 * D_;
        repack_k<<<(int)((total + 255) / 256), 256>>>(Wq, Wk, Wv, wqkv);
    }
    embed_k<<<(M_ * D_ + 255) / 256, 256>>>(idx, tok, pos, x);

    for (int l = 0; l < L_; l++) {
        ln_k<<<M_, 128>>>(x, y, ln1g + (long)l * D_, ln1b + (long)l * D_);
        { dim3 g(9, 128);  gemm128_k<<<g, 256>>>(y, wqkv + (long)l * D_ * 3 * D_, (const float*)0, (const float*)0, qkv, 3 * D_, D_, 0); }
        attn_k<<<B_ * H_, 256, attn_smem>>>(qkv, o);
        { dim3 g(3, 128);  gemm128_k<<<g, 256>>>(o, Wproj + (long)l * D_ * D_, bproj + (long)l * D_, x, x, D_, D_, 0); }
        ln_k<<<M_, 128>>>(x, y, ln1g + (long)l * D_, ln1b + (long)l * D_);   // faithful: reuses ln1
        { dim3 g(12, 128); gemm128_k<<<g, 256>>>(y, W1 + (long)l * D_ * FF_, b1 + (long)l * FF_, (const float*)0, h1, FF_, D_, 1); }
        { dim3 g(3, 128);  gemm128_k<<<g, 256>>>(h1, W2 + (long)l * FF_ * D_, b2 + (long)l * D_, x, x, D_, FF_, 0); }
    }

    ln_k<<<M_, 128>>>(x, y, lnfg, lnfb);
    { dim3 g(1, 128); gemm_k<<<g, 256>>>(y, Whead, bhead, (const float*)0, logits, V_, D_, 0); }
    loss_k<<<2048, 256>>>(logits, targets, part);
    finalize_k<<<1, 256>>>(out, (long)out_size, part);
}

// round 8
// speedup vs baseline: 2.6972x; 1.6282x over previous
#include <cuda_runtime.h>
#include <cuda_bf16.h>
#include <math.h>
#include <cstdint>

#define B_  64
#define T_  256
#define D_  384
#define H_  6
#define HS_ 64
#define L_  6
#define V_  65
#define FF_ 1536
#define M_  (B_*T_)   // 16384 tokens

// ---------------- scratch (device globals; no allocation allowed) ----------------
__device__ float g_x[M_*D_];            // residual stream (f32)
__device__ float g_y[M_*D_];            // f32 LN out (final LN / head only)
__device__ float g_qkv[M_*3*D_];        // fused qkv (f32)
__device__ float g_logits[M_*V_];       // fallback logits buffer
__device__ float g_losspart[2048];

// split-bf16 activation buffers
__device__ __nv_bfloat16 g_yh[M_*D_],  g_yl[M_*D_];
__device__ __nv_bfloat16 g_oh[M_*D_],  g_ol[M_*D_];
__device__ __nv_bfloat16 g_h1h[M_*FF_], g_h1l[M_*FF_];

// split-bf16 transposed weights [N][K]
__device__ __nv_bfloat16 g_wqkvh[L_*3*D_*D_],  g_wqkvl[L_*3*D_*D_];   // N=1152,K=384
__device__ __nv_bfloat16 g_wprojh[L_*D_*D_],   g_wprojl[L_*D_*D_];    // N=384, K=384
__device__ __nv_bfloat16 g_w1h[L_*FF_*D_],     g_w1l[L_*FF_*D_];      // N=1536,K=384
__device__ __nv_bfloat16 g_w2h[L_*D_*FF_],     g_w2l[L_*D_*FF_];      // N=384, K=1536

// ---------------- helpers ----------------
static __device__ __forceinline__ uint32_t s2u(const void* p) {
    uint32_t a;
    asm("{ .reg .u64 t; cvta.to.shared.u64 t, %1; cvt.u32.u64 %0, t; }" : "=r"(a) : "l"(p));
    return a;
}
static __device__ __forceinline__ void split2(float v, __nv_bfloat16& hi, __nv_bfloat16& lo) {
    hi = __float2bfloat16(v);
    lo = __float2bfloat16(v - __bfloat162float(hi));
}
static __device__ __forceinline__ void ldmx4(uint32_t* r, uint32_t addr) {
    asm volatile("ldmatrix.sync.aligned.m8n8.x4.shared.b16 {%0,%1,%2,%3}, [%4];"
                 : "=r"(r[0]), "=r"(r[1]), "=r"(r[2]), "=r"(r[3]) : "r"(addr));
}
static __device__ __forceinline__ void mma16816(float* c, const uint32_t* a,
                                                uint32_t b0, uint32_t b1) {
    asm volatile(
        "mma.sync.aligned.m16n8k16.row.col.f32.bf16.bf16.f32 "
        "{%0,%1,%2,%3}, {%4,%5,%6,%7}, {%8,%9}, {%0,%1,%2,%3};"
        : "+f"(c[0]), "+f"(c[1]), "+f"(c[2]), "+f"(c[3])
        : "r"(a[0]), "r"(a[1]), "r"(a[2]), "r"(a[3]), "r"(b0), "r"(b1));
}
static __device__ __forceinline__ void cpasync16(uint32_t dst, const void* src) {
    asm volatile("cp.async.cg.shared.global [%0], [%1], 16;" :: "r"(dst), "l"(src) : "memory");
}

// ---------------- weight conversion ----------------
// Wq/Wk/Wv [L,H,D,HS] -> [L, N=1152, K=384] split bf16
__global__ void convqkv_k(const float* __restrict__ Wq, const float* __restrict__ Wk,
                          const float* __restrict__ Wv,
                          __nv_bfloat16* __restrict__ oh, __nv_bfloat16* __restrict__ ol) {
    long i = (long)blockIdx.x * blockDim.x + threadIdx.x;
    const long total = (long)L_ * 3 * D_ * D_;
    if (i >= total) return;
    int k = (int)(i % D_);
    long t = i / D_;
    int n = (int)(t % (3 * D_));
    int l = (int)(t / (3 * D_));
    const float* W; int cc;
    if (n < D_)          { W = Wq; cc = n; }
    else if (n < 2 * D_) { W = Wk; cc = n - D_; }
    else                 { W = Wv; cc = n - 2 * D_; }
    int h = cc / HS_, e = cc % HS_;
    float v = W[(((long)l * H_ + h) * D_ + k) * HS_ + e];
    split2(v, oh[i], ol[i]);
}

// generic [L][K][N] -> [L][N][K] transpose + split
__global__ void convt_k(const float* __restrict__ in,
                        __nv_bfloat16* __restrict__ oh, __nv_bfloat16* __restrict__ ol,
                        int Kd, int Nd) {
    long i = (long)blockIdx.x * blockDim.x + threadIdx.x;
    const long total = (long)L_ * Nd * Kd;
    if (i >= total) return;
    int k = (int)(i % Kd);
    long t = i / Kd;
    int n = (int)(t % Nd);
    int l = (int)(t / Nd);
    float v = in[((long)l * Kd + k) * Nd + n];
    split2(v, oh[i], ol[i]);
}

// ---------------- embedding ----------------
__global__ void embed_k(const int* __restrict__ idx, const float* __restrict__ tok,
                        const float* __restrict__ pos, float* __restrict__ x) {
    int i = blockIdx.x * blockDim.x + threadIdx.x;
    if (i >= M_ * D_) return;
    int d = i % D_;
    int r = i / D_;
    int t = r % T_;
    x[i] = tok[(long)idx[r] * D_ + d] + pos[(long)t * D_ + d];
}

// ---------------- layernorm: optional f32 out + optional split-bf16 out ----------------
__global__ void ln_k(const float* __restrict__ x, float* __restrict__ y,
                     __nv_bfloat16* __restrict__ yh, __nv_bfloat16* __restrict__ yl,
                     const float* __restrict__ g, const float* __restrict__ b) {
    int row = blockIdx.x;
    const float* xr = x + (long)row * D_;
    float s = 0.f, s2 = 0.f;
    for (int d = threadIdx.x; d < D_; d += 128) { float v = xr[d]; s += v; s2 += v * v; }
    #pragma unroll
    for (int o = 16; o; o >>= 1) {
        s  += __shfl_xor_sync(0xffffffffu, s,  o);
        s2 += __shfl_xor_sync(0xffffffffu, s2, o);
    }
    __shared__ float ss[4], ss2[4];
    int w = threadIdx.x >> 5;
    if ((threadIdx.x & 31) == 0) { ss[w] = s; ss2[w] = s2; }
    __syncthreads();
    s  = ss[0] + ss[1] + ss[2] + ss[3];
    s2 = ss2[0] + ss2[1] + ss2[2] + ss2[3];
    float mean = s * (1.f / D_);
    float var  = s2 * (1.f / D_) - mean * mean;
    float inv  = rsqrtf(var + 1e-5f);
    for (int d = threadIdx.x; d < D_; d += 128) {
        float v = (xr[d] - mean) * inv * g[d] + b[d];
        if (y) y[(long)row * D_ + d] = v;
        if (yh) split2(v, yh[(long)row * D_ + d], yl[(long)row * D_ + d]);
    }
}

// ---------------- mma.sync split-bf16 GEMM ----------------
// D[m,n] = sum_k A[m,k]*B[n,k], 3-pass split bf16 into f32 acc.
// 128x128 CTA tile, 8 warps (2x4), warp tile 64x32, m16n8k16 atoms.
// K chunks of 32, cp.async double buffer, padded smem rows (stride 40 bf16).
#define GSTRIDE 40
#define GTILE   (128*GSTRIDE)      // bf16 per tile
#define GBUF    (4*GTILE)          // bf16 per buffer (Ah,Al,Bh,Bl)
__global__ void __launch_bounds__(256)
gemm_bf16_k(const __nv_bfloat16* __restrict__ Ah, const __nv_bfloat16* __restrict__ Al,
            const __nv_bfloat16* __restrict__ Bh, const __nv_bfloat16* __restrict__ Bl,
            const float* __restrict__ bias, const float* __restrict__ Cin,
            float* __restrict__ C,
            __nv_bfloat16* __restrict__ Oh, __nv_bfloat16* __restrict__ Ol,
            int N, int K, int relu) {
    extern __shared__ __align__(16) char smem[];
    uint32_t sb = s2u(smem);
    int tid = threadIdx.x, wid = tid >> 5, lane = tid & 31;
    int wm = wid >> 2, wn = wid & 3;          // warp grid 2x4
    int m0 = blockIdx.y * 128, n0 = blockIdx.x * 128;

    float acc[4][4][4];
    #pragma unroll
    for (int i = 0; i < 4; i++)
        #pragma unroll
        for (int j = 0; j < 4; j++)
            #pragma unroll
            for (int q = 0; q < 4; q++) acc[i][j][q] = 0.f;

    // ldmatrix lane addressing
    int sel  = lane >> 3;
    int arow = (lane & 7) + ((sel & 1) << 3);
    int acol = (sel >> 1) << 3;
    int brow = (lane & 7) + ((sel >> 1) << 3);
    int bcol = (sel & 1) << 3;

    const int nch = K >> 5;   // K/32

    // per-thread global->smem slices: 512 16B-chunks per tile, 2 per thread
    int r0i = (tid * 2) >> 2,       c0i = ((tid * 2) & 3) * 8;
    int r1i = (tid * 2 + 1) >> 2,   c1i = ((tid * 2 + 1) & 3) * 8;

    #define ISSUE(ch, buf) do { \
        int kc = (ch) * 32; \
        const __nv_bfloat16* srcs[4] = {Ah, Al, Bh, Bl}; \
        _Pragma("unroll") \
        for (int tt = 0; tt < 4; tt++) { \
            const __nv_bfloat16* sp = srcs[tt]; \
            int rb = (tt < 2) ? m0 : n0; \
            uint32_t db = sb + ((buf) * GBUF + tt * GTILE) * 2; \
            cpasync16(db + (r0i * GSTRIDE + c0i) * 2, sp + (long)(rb + r0i) * K + kc + c0i); \
            cpasync16(db + (r1i * GSTRIDE + c1i) * 2, sp + (long)(rb + r1i) * K + kc + c1i); \
        } \
        asm volatile("cp.async.commit_group;" ::: "memory"); \
    } while (0)

    ISSUE(0, 0);

    for (int ch = 0; ch < nch; ch++) {
        if (ch + 1 < nch) {
            ISSUE(ch + 1, (ch + 1) & 1);
            asm volatile("cp.async.wait_group 1;" ::: "memory");
        } else {
            asm volatile("cp.async.wait_group 0;" ::: "memory");
        }
        __syncthreads();

        uint32_t base = sb + ((ch & 1) * GBUF) * 2;
        uint32_t tAh = base;
        uint32_t tAl = base + GTILE * 2;
        uint32_t tBh = base + 2 * GTILE * 2;
        uint32_t tBl = base + 3 * GTILE * 2;

        #pragma unroll
        for (int ks = 0; ks < 2; ks++) {
            int k0 = ks * 16;
            uint32_t ahf[4][4], alf[4][4];
            #pragma unroll
            for (int mf = 0; mf < 4; mf++) {
                uint32_t off = ((wm * 64 + mf * 16 + arow) * GSTRIDE + k0 + acol) * 2;
                ldmx4(ahf[mf], tAh + off);
                ldmx4(alf[mf], tAl + off);
            }
            uint32_t bhf[2][4], blf[2][4];
            #pragma unroll
            for (int ng = 0; ng < 2; ng++) {
                uint32_t off = ((wn * 32 + ng * 16 + brow) * GSTRIDE + k0 + bcol) * 2;
                ldmx4(bhf[ng], tBh + off);
                ldmx4(blf[ng], tBl + off);
            }
            #pragma unroll
            for (int mf = 0; mf < 4; mf++) {
                #pragma unroll
                for (int ng = 0; ng < 2; ng++) {
                    mma16816(acc[mf][ng * 2],     ahf[mf], bhf[ng][0], bhf[ng][1]);
                    mma16816(acc[mf][ng * 2 + 1], ahf[mf], bhf[ng][2], bhf[ng][3]);
                    mma16816(acc[mf][ng * 2],     ahf[mf], blf[ng][0], blf[ng][1]);
                    mma16816(acc[mf][ng * 2 + 1], ahf[mf], blf[ng][2], blf[ng][3]);
                    mma16816(acc[mf][ng * 2],     alf[mf], bhf[ng][0], bhf[ng][1]);
                    mma16816(acc[mf][ng * 2 + 1], alf[mf], bhf[ng][2], bhf[ng][3]);
                }
            }
        }
        __syncthreads();
    }

    // epilogue: thread holds rows (tr, tr+8), col pair tc within each atom
    int tr = lane >> 2, tc = (lane & 3) * 2;
    #pragma unroll
    for (int mf = 0; mf < 4; mf++) {
        #pragma unroll
        for (int half = 0; half < 2; half++) {
            long row = m0 + wm * 64 + mf * 16 + tr + half * 8;
            #pragma unroll
            for (int nf = 0; nf < 4; nf++) {
                int col = n0 + wn * 32 + nf * 8 + tc;
                float v0 = acc[mf][nf][half * 2 + 0];
                float v1 = acc[mf][nf][half * 2 + 1];
                if (bias) { v0 += bias[col]; v1 += bias[col + 1]; }
                if (Cin) {
                    float2 ci = *(const float2*)(Cin + row * (long)N + col);
                    v0 += ci.x; v1 += ci.y;
                }
                if (relu) { v0 = fmaxf(v0, 0.f); v1 = fmaxf(v1, 0.f); }
                if (C) *(float2*)(C + row * (long)N + col) = make_float2(v0, v1);
                if (Oh) {
                    __nv_bfloat16 h0, l0, h1, l1;
                    split2(v0, h0, l0); split2(v1, h1, l1);
                    __nv_bfloat16 hp[2] = {h0, h1}, lp[2] = {l0, l1};
                    *(uint32_t*)(Oh + row * (long)N + col) = *(uint32_t*)hp;
                    *(uint32_t*)(Ol + row * (long)N + col) = *(uint32_t*)lp;
                }
            }
        }
    }
}

// ---------------- small-N fp32 GEMM (head, N=65) ----------------
__global__ void gemm_k(const float* __restrict__ A, const float* __restrict__ Bw,
                       const float* __restrict__ bias, float* __restrict__ C,
                       int N, int K) {
    __shared__ float As[8][128];
    __shared__ float Bs[8][128];
    int tid = threadIdx.x;
    int m0 = blockIdx.y * 128, n0 = blockIdx.x * 128;
    int arow = tid >> 1, ac4 = (tid & 1) * 4;
    int brow = tid >> 5, bcol = (tid & 31) * 4;
    int ty = tid >> 4, tx = tid & 15;

    float acc[8][8];
    #pragma unroll
    for (int i = 0; i < 8; i++)
        #pragma unroll
        for (int j = 0; j < 8; j++) acc[i][j] = 0.f;

    const float* Aptr = A + (long)(m0 + arow) * K + ac4;

    for (int kt = 0; kt < K; kt += 8) {
        float4 av = *(const float4*)(Aptr + kt);
        As[ac4 + 0][arow] = av.x; As[ac4 + 1][arow] = av.y;
        As[ac4 + 2][arow] = av.z; As[ac4 + 3][arow] = av.w;

        int col = n0 + bcol;
        const float* bp = Bw + (long)(kt + brow) * N;
        float4 bv;
        bv.x = (col + 0 < N) ? bp[col + 0] : 0.f;
        bv.y = (col + 1 < N) ? bp[col + 1] : 0.f;
        bv.z = (col + 2 < N) ? bp[col + 2] : 0.f;
        bv.w = (col + 3 < N) ? bp[col + 3] : 0.f;
        *(float4*)&Bs[brow][bcol] = bv;
        __syncthreads();

        #pragma unroll
        for (int kk = 0; kk < 8; kk++) {
            float a[8], bb[8];
            *(float4*)&a[0]  = *(const float4*)&As[kk][ty * 8];
            *(float4*)&a[4]  = *(const float4*)&As[kk][ty * 8 + 4];
            *(float4*)&bb[0] = *(const float4*)&Bs[kk][tx * 8];
            *(float4*)&bb[4] = *(const float4*)&Bs[kk][tx * 8 + 4];
            #pragma unroll
            for (int i = 0; i < 8; i++)
                #pragma unroll
                for (int j = 0; j < 8; j++) acc[i][j] += a[i] * bb[j];
        }
        __syncthreads();
    }

    #pragma unroll
    for (int i = 0; i < 8; i++) {
        long row = m0 + ty * 8 + i;
        float* crow = C + row * (long)N;
        #pragma unroll
        for (int j = 0; j < 8; j++) {
            int col = n0 + tx * 8 + j;
            if (col < N) crow[col] = acc[i][j] + (bias ? bias[col] : 0.f);
        }
    }
}

// ---------------- fused causal attention (f32), split-bf16 output ----------------
__global__ void attn_k(const float* __restrict__ qkv,
                       __nv_bfloat16* __restrict__ oh, __nv_bfloat16* __restrict__ ol) {
    extern __shared__ float smf[];
    float* Ks = smf;
    float* Vs = smf + T_ * HS_;
    int bh = blockIdx.x;
    int b = bh / H_, h = bh % H_;
    int t = threadIdx.x;
    const long base = (long)b * T_ * 3 * D_;

    for (int i = t; i < T_ * (HS_ / 4); i += blockDim.x) {
        int row = i / (HS_ / 4);
        int c4  = i % (HS_ / 4);
        const float* krow = qkv + base + (long)row * 3 * D_ + D_     + h * HS_;
        const float* vrow = qkv + base + (long)row * 3 * D_ + 2 * D_ + h * HS_;
        ((float4*)Ks)[i] = ((const float4*)krow)[c4];
        ((float4*)Vs)[i] = ((const float4*)vrow)[c4];
    }
    __syncthreads();

    float4 qv[16];
    {
        const float4* qp = (const float4*)(qkv + base + (long)t * 3 * D_ + h * HS_);
        #pragma unroll
        for (int j = 0; j < 16; j++) qv[j] = qp[j];
    }
    const float scale = 0.05103103630798288f;  // 384^-0.5

    float m = -1e30f, lsum = 0.f;
    float acc[HS_];
    #pragma unroll
    for (int e = 0; e < HS_; e++) acc[e] = 0.f;

    for (int tk = 0; tk <= t; tk++) {
        const float4* kr = (const float4*)(Ks + tk * HS_);
        float s = 0.f;
        #pragma unroll
        for (int j = 0; j < 16; j++) {
            float4 k4 = kr[j];
            s += qv[j].x * k4.x + qv[j].y * k4.y + qv[j].z * k4.z + qv[j].w * k4.w;
        }
        s *= scale;
        const float* vr = Vs + tk * HS_;
        if (s > m) {
            float c = __expf(m - s);
            lsum = lsum * c + 1.f;
            #pragma unroll
            for (int e = 0; e < HS_; e++) acc[e] = acc[e] * c + vr[e];
            m = s;
        } else {
            float p = __expf(s - m);
            lsum += p;
            #pragma unroll
            for (int e = 0; e < HS_; e++) acc[e] += p * vr[e];
        }
    }
    float rl = 1.f / lsum;
    long rb = ((long)b * T_ + t) * D_ + h * HS_;
    #pragma unroll
    for (int e = 0; e < HS_; e++) {
        float v = acc[e] * rl;
        split2(v, oh[rb + e], ol[rb + e]);
    }
}

// ---------------- loss ----------------
__global__ void loss_k(const float* __restrict__ logits, const int* __restrict__ targets,
                       float* __restrict__ part) {
    int gwarp = (blockIdx.x * blockDim.x + threadIdx.x) >> 5;
    int lane = threadIdx.x & 31;
    const float* lr = logits + (long)gwarp * V_;
    float mx = -1e30f;
    for (int c = lane; c < V_; c += 32) mx = fmaxf(mx, lr[c]);
    #pragma unroll
    for (int o = 16; o; o >>= 1) mx = fmaxf(mx, __shfl_xor_sync(0xffffffffu, mx, o));
    float se = 0.f;
    for (int c = lane; c < V_; c += 32) se += expf(lr[c] - mx);
    #pragma unroll
    for (int o = 16; o; o >>= 1) se += __shfl_xor_sync(0xffffffffu, se, o);
    float li = (mx + logf(se)) - lr[targets[gwarp]];
    __shared__ float ws[8];
    if (lane == 0) ws[threadIdx.x >> 5] = li;
    __syncthreads();
    if (threadIdx.x == 0) {
        float s = 0.f;
        #pragma unroll
        for (int i = 0; i < 8; i++) s += ws[i];
        part[blockIdx.x] = s;
    }
}

__global__ void finalize_k(float* out, long out_size, const float* __restrict__ part) {
    float v = 0.f;
    for (int i = threadIdx.x; i < 2048; i += 256) v += part[i];
    #pragma unroll
    for (int o = 16; o; o >>= 1) v += __shfl_xor_sync(0xffffffffu, v, o);
    __shared__ float sm[8];
    if ((threadIdx.x & 31) == 0) sm[threadIdx.x >> 5] = v;
    __syncthreads();
    if (threadIdx.x == 0) {
        float s = 0.f;
        #pragma unroll
        for (int i = 0; i < 8; i++) s += sm[i];
        float loss = s / (float)M_;
        const long btv = (long)M_ * V_;
        if (out_size > btv)       out[btv] = loss;
        else if (out_size == 1)   out[0]   = loss;
    }
}

// ---------------- driver ----------------
extern "C" void kernel_launch(void* const* d_in, const int* in_sizes, int n_in,
                              void* d_out, int out_size) {
    const int*   idx     = (const int*)d_in[0];
    const int*   targets = (const int*)d_in[1];
    const float* tok     = (const float*)d_in[2];
    const float* pos     = (const float*)d_in[3];
    const float* Wq      = (const float*)d_in[4];
    const float* Wk      = (const float*)d_in[5];
    const float* Wv      = (const float*)d_in[6];
    const float* Wproj   = (const float*)d_in[7];
    const float* bproj   = (const float*)d_in[8];
    const float* W1      = (const float*)d_in[9];
    const float* b1      = (const float*)d_in[10];
    const float* W2      = (const float*)d_in[11];
    const float* b2      = (const float*)d_in[12];
    const float* ln1g    = (const float*)d_in[13];
    const float* ln1b    = (const float*)d_in[14];
    const float* lnfg    = (const float*)d_in[15];
    const float* lnfb    = (const float*)d_in[16];
    const float* Whead   = (const float*)d_in[17];
    const float* bhead   = (const float*)d_in[18];
    float* out = (float*)d_out;

    float *x, *y, *qkv, *lgts, *part;
    __nv_bfloat16 *yh, *yl, *oh, *ol, *h1h, *h1l;
    __nv_bfloat16 *wqh, *wql, *wph, *wpl, *w1h, *w1l, *w2h, *w2l;
    cudaGetSymbolAddress((void**)&x,    g_x);
    cudaGetSymbolAddress((void**)&y,    g_y);
    cudaGetSymbolAddress((void**)&qkv,  g_qkv);
    cudaGetSymbolAddress((void**)&lgts, g_logits);
    cudaGetSymbolAddress((void**)&part, g_losspart);
    cudaGetSymbolAddress((void**)&yh,   g_yh);
    cudaGetSymbolAddress((void**)&yl,   g_yl);
    cudaGetSymbolAddress((void**)&oh,   g_oh);
    cudaGetSymbolAddress((void**)&ol,   g_ol);
    cudaGetSymbolAddress((void**)&h1h,  g_h1h);
    cudaGetSymbolAddress((void**)&h1l,  g_h1l);
    cudaGetSymbolAddress((void**)&wqh,  g_wqkvh);
    cudaGetSymbolAddress((void**)&wql,  g_wqkvl);
    cudaGetSymbolAddress((void**)&wph,  g_wprojh);
    cudaGetSymbolAddress((void**)&wpl,  g_wprojl);
    cudaGetSymbolAddress((void**)&w1h,  g_w1h);
    cudaGetSymbolAddress((void**)&w1l,  g_w1l);
    cudaGetSymbolAddress((void**)&w2h,  g_w2h);
    cudaGetSymbolAddress((void**)&w2l,  g_w2l);

    const int attn_smem = 2 * T_ * HS_ * 4;       // 128 KB
    cudaFuncSetAttribute(attn_k, cudaFuncAttributeMaxDynamicSharedMemorySize, attn_smem);
    const int gsmem = 2 * GBUF * 2;               // 81920 B
    cudaFuncSetAttribute(gemm_bf16_k, cudaFuncAttributeMaxDynamicSharedMemorySize, gsmem);

    const long btv = (long)M_ * V_;
    float* logits = ((long)out_size >= btv) ? out : lgts;

    // weight conversion (split bf16, transposed to [N][K])
    {
        long tq = (long)L_ * 3 * D_ * D_;
        convqkv_k<<<(int)((tq + 255) / 256), 256>>>(Wq, Wk, Wv, wqh, wql);
        long tp = (long)L_ * D_ * D_;
        convt_k<<<(int)((tp + 255) / 256), 256>>>(Wproj, wph, wpl, D_, D_);
        long t1 = (long)L_ * FF_ * D_;
        convt_k<<<(int)((t1 + 255) / 256), 256>>>(W1, w1h, w1l, D_, FF_);
        long t2 = (long)L_ * D_ * FF_;
        convt_k<<<(int)((t2 + 255) / 256), 256>>>(W2, w2h, w2l, FF_, D_);
    }
    embed_k<<<(M_ * D_ + 255) / 256, 256>>>(idx, tok, pos, x);

    for (int l = 0; l < L_; l++) {
        ln_k<<<M_, 128>>>(x, (float*)0, yh, yl, ln1g + (long)l * D_, ln1b + (long)l * D_);
        { dim3 g(9, 128);
          gemm_bf16_k<<<g, 256, gsmem>>>(yh, yl,
              wqh + (long)l * 3 * D_ * D_, wql + (long)l * 3 * D_ * D_,
              (const float*)0, (const float*)0, qkv,
              (__nv_bfloat16*)0, (__nv_bfloat16*)0, 3 * D_, D_, 0); }
        attn_k<<<B_ * H_, 256, attn_smem>>>(qkv, oh, ol);
        { dim3 g(3, 128);
          gemm_bf16_k<<<g, 256, gsmem>>>(oh, ol,
              wph + (long)l * D_ * D_, wpl + (long)l * D_ * D_,
              bproj + (long)l * D_, x, x,
              (__nv_bfloat16*)0, (__nv_bfloat16*)0, D_, D_, 0); }
        ln_k<<<M_, 128>>>(x, (float*)0, yh, yl, ln1g + (long)l * D_, ln1b + (long)l * D_);
        { dim3 g(12, 128);
          gemm_bf16_k<<<g, 256, gsmem>>>(yh, yl,
              w1h + (long)l * FF_ * D_, w1l + (long)l * FF_ * D_,
              b1 + (long)l * FF_, (const float*)0, (float*)0,
              h1h, h1l, FF_, D_, 1); }
        { dim3 g(3, 128);
          gemm_bf16_k<<<g, 256, gsmem>>>(h1h, h1l,
              w2h + (long)l * D_ * FF_, w2l + (long)l * D_ * FF_,
              b2 + (long)l * D_, x, x,
              (__nv_bfloat16*)0, (__nv_bfloat16*)0, D_, FF_, 0); }
    }

    ln_k<<<M_, 128>>>(x, y, (__nv_bfloat16*)0, (__nv_bfloat16*)0, lnfg, lnfb);
    { dim3 g(1, 128); gemm_k<<<g, 256>>>(y, Whead, bhead, logits, V_, D_); }
    loss_k<<<2048, 256>>>(logits, targets, part);
    finalize_k<<<1, 256>>>(out, (long)out_size, part);
}

// round 12
// speedup vs baseline: 3.7499x; 1.3903x over previous
#include <cuda_runtime.h>
#include <cuda_bf16.h>
#include <math.h>
#include <cstdint>

#define B_  64
#define T_  256
#define D_  384
#define H_  6
#define HS_ 64
#define L_  6
#define V_  65
#define FF_ 1536
#define M_  (B_*T_)   // 16384 tokens

// ---------------- scratch (device globals; no allocation allowed) ----------------
__device__ float g_x[M_*D_];            // residual stream (f32)
__device__ float g_y[M_*D_];            // f32 LN out (final LN / head only)
__device__ float g_qkv[M_*3*D_];        // fused qkv (f32)
__device__ float g_logits[M_*V_];       // fallback logits buffer
__device__ float g_losspart[2048];

// split-bf16 activation buffers
__device__ __nv_bfloat16 g_yh[M_*D_],  g_yl[M_*D_];
__device__ __nv_bfloat16 g_oh[M_*D_],  g_ol[M_*D_];
__device__ __nv_bfloat16 g_h1h[M_*FF_], g_h1l[M_*FF_];

// split-bf16 transposed weights [N][K]
__device__ __nv_bfloat16 g_wqkvh[L_*3*D_*D_],  g_wqkvl[L_*3*D_*D_];   // N=1152,K=384
__device__ __nv_bfloat16 g_wprojh[L_*D_*D_],   g_wprojl[L_*D_*D_];    // N=384, K=384
__device__ __nv_bfloat16 g_w1h[L_*FF_*D_],     g_w1l[L_*FF_*D_];      // N=1536,K=384
__device__ __nv_bfloat16 g_w2h[L_*D_*FF_],     g_w2l[L_*D_*FF_];      // N=384, K=1536

// ---------------- helpers ----------------
static __device__ __forceinline__ uint32_t s2u(const void* p) {
    uint32_t a;
    asm("{ .reg .u64 t; cvta.to.shared.u64 t, %1; cvt.u32.u64 %0, t; }" : "=r"(a) : "l"(p));
    return a;
}
static __device__ __forceinline__ void split2(float v, __nv_bfloat16& hi, __nv_bfloat16& lo) {
    hi = __float2bfloat16(v);
    lo = __float2bfloat16(v - __bfloat162float(hi));
}
static __device__ __forceinline__ void ldmx4(uint32_t* r, uint32_t addr) {
    asm volatile("ldmatrix.sync.aligned.m8n8.x4.shared.b16 {%0,%1,%2,%3}, [%4];"
                 : "=r"(r[0]), "=r"(r[1]), "=r"(r[2]), "=r"(r[3]) : "r"(addr));
}
static __device__ __forceinline__ void ldmx4t(uint32_t* r, uint32_t addr) {
    asm volatile("ldmatrix.sync.aligned.m8n8.x4.trans.shared.b16 {%0,%1,%2,%3}, [%4];"
                 : "=r"(r[0]), "=r"(r[1]), "=r"(r[2]), "=r"(r[3]) : "r"(addr));
}
static __device__ __forceinline__ void mma16816(float* c, const uint32_t* a,
                                                uint32_t b0, uint32_t b1) {
    asm volatile(
        "mma.sync.aligned.m16n8k16.row.col.f32.bf16.bf16.f32 "
        "{%0,%1,%2,%3}, {%4,%5,%6,%7}, {%8,%9}, {%0,%1,%2,%3};"
        : "+f"(c[0]), "+f"(c[1]), "+f"(c[2]), "+f"(c[3])
        : "r"(a[0]), "r"(a[1]), "r"(a[2]), "r"(a[3]), "r"(b0), "r"(b1));
}
static __device__ __forceinline__ void cpasync16(uint32_t dst, const void* src) {
    asm volatile("cp.async.cg.shared.global [%0], [%1], 16;" :: "r"(dst), "l"(src) : "memory");
}
static __device__ __forceinline__ uint32_t pk2f(float lo, float hi) {
    uint32_t r;
    asm("cvt.rn.bf16x2.f32 %0, %1, %2;" : "=r"(r) : "f"(hi), "f"(lo));
    return r;
}

// ---------------- weight conversion ----------------
__global__ void convqkv_k(const float* __restrict__ Wq, const float* __restrict__ Wk,
                          const float* __restrict__ Wv,
                          __nv_bfloat16* __restrict__ oh, __nv_bfloat16* __restrict__ ol) {
    long i = (long)blockIdx.x * blockDim.x + threadIdx.x;
    const long total = (long)L_ * 3 * D_ * D_;
    if (i >= total) return;
    int k = (int)(i % D_);
    long t = i / D_;
    int n = (int)(t % (3 * D_));
    int l = (int)(t / (3 * D_));
    const float* W; int cc;
    if (n < D_)          { W = Wq; cc = n; }
    else if (n < 2 * D_) { W = Wk; cc = n - D_; }
    else                 { W = Wv; cc = n - 2 * D_; }
    int h = cc / HS_, e = cc % HS_;
    float v = W[(((long)l * H_ + h) * D_ + k) * HS_ + e];
    split2(v, oh[i], ol[i]);
}

__global__ void convt_k(const float* __restrict__ in,
                        __nv_bfloat16* __restrict__ oh, __nv_bfloat16* __restrict__ ol,
                        int Kd, int Nd) {
    long i = (long)blockIdx.x * blockDim.x + threadIdx.x;
    const long total = (long)L_ * Nd * Kd;
    if (i >= total) return;
    int k = (int)(i % Kd);
    long t = i / Kd;
    int n = (int)(t % Nd);
    int l = (int)(t / Nd);
    float v = in[((long)l * Kd + k) * Nd + n];
    split2(v, oh[i], ol[i]);
}

// ---------------- embedding ----------------
__global__ void embed_k(const int* __restrict__ idx, const float* __restrict__ tok,
                        const float* __restrict__ pos, float* __restrict__ x) {
    int i = blockIdx.x * blockDim.x + threadIdx.x;
    if (i >= M_ * D_) return;
    int d = i % D_;
    int r = i / D_;
    int t = r % T_;
    x[i] = tok[(long)idx[r] * D_ + d] + pos[(long)t * D_ + d];
}

// ---------------- layernorm ----------------
__global__ void ln_k(const float* __restrict__ x, float* __restrict__ y,
                     __nv_bfloat16* __restrict__ yh, __nv_bfloat16* __restrict__ yl,
                     const float* __restrict__ g, const float* __restrict__ b) {
    int row = blockIdx.x;
    const float* xr = x + (long)row * D_;
    float s = 0.f, s2 = 0.f;
    for (int d = threadIdx.x; d < D_; d += 128) { float v = xr[d]; s += v; s2 += v * v; }
    #pragma unroll
    for (int o = 16; o; o >>= 1) {
        s  += __shfl_xor_sync(0xffffffffu, s,  o);
        s2 += __shfl_xor_sync(0xffffffffu, s2, o);
    }
    __shared__ float ss[4], ss2[4];
    int w = threadIdx.x >> 5;
    if ((threadIdx.x & 31) == 0) { ss[w] = s; ss2[w] = s2; }
    __syncthreads();
    s  = ss[0] + ss[1] + ss[2] + ss[3];
    s2 = ss2[0] + ss2[1] + ss2[2] + ss2[3];
    float mean = s * (1.f / D_);
    float var  = s2 * (1.f / D_) - mean * mean;
    float inv  = rsqrtf(var + 1e-5f);
    for (int d = threadIdx.x; d < D_; d += 128) {
        float v = (xr[d] - mean) * inv * g[d] + b[d];
        if (y) y[(long)row * D_ + d] = v;
        if (yh) split2(v, yh[(long)row * D_ + d], yl[(long)row * D_ + d]);
    }
}

// ---------------- mma.sync split-bf16 GEMM (validated R8) ----------------
#define GSTRIDE 40
#define GTILE   (128*GSTRIDE)
#define GBUF    (4*GTILE)
__global__ void __launch_bounds__(256)
gemm_bf16_k(const __nv_bfloat16* __restrict__ Ah, const __nv_bfloat16* __restrict__ Al,
            const __nv_bfloat16* __restrict__ Bh, const __nv_bfloat16* __restrict__ Bl,
            const float* __restrict__ bias, const float* __restrict__ Cin,
            float* __restrict__ C,
            __nv_bfloat16* __restrict__ Oh, __nv_bfloat16* __restrict__ Ol,
            int N, int K, int relu) {
    extern __shared__ __align__(16) char smem[];
    uint32_t sb = s2u(smem);
    int tid = threadIdx.x, wid = tid >> 5, lane = tid & 31;
    int wm = wid >> 2, wn = wid & 3;
    int m0 = blockIdx.y * 128, n0 = blockIdx.x * 128;

    float acc[4][4][4];
    #pragma unroll
    for (int i = 0; i < 4; i++)
        #pragma unroll
        for (int j = 0; j < 4; j++)
            #pragma unroll
            for (int q = 0; q < 4; q++) acc[i][j][q] = 0.f;

    int sel  = lane >> 3;
    int arow = (lane & 7) + ((sel & 1) << 3);
    int acol = (sel >> 1) << 3;
    int brow = (lane & 7) + ((sel >> 1) << 3);
    int bcol = (sel & 1) << 3;

    const int nch = K >> 5;
    int r0i = (tid * 2) >> 2,       c0i = ((tid * 2) & 3) * 8;
    int r1i = (tid * 2 + 1) >> 2,   c1i = ((tid * 2 + 1) & 3) * 8;

    #define ISSUE(ch, buf) do { \
        int kc = (ch) * 32; \
        const __nv_bfloat16* srcs[4] = {Ah, Al, Bh, Bl}; \
        _Pragma("unroll") \
        for (int tt = 0; tt < 4; tt++) { \
            const __nv_bfloat16* sp = srcs[tt]; \
            int rb = (tt < 2) ? m0 : n0; \
            uint32_t db = sb + ((buf) * GBUF + tt * GTILE) * 2; \
            cpasync16(db + (r0i * GSTRIDE + c0i) * 2, sp + (long)(rb + r0i) * K + kc + c0i); \
            cpasync16(db + (r1i * GSTRIDE + c1i) * 2, sp + (long)(rb + r1i) * K + kc + c1i); \
        } \
        asm volatile("cp.async.commit_group;" ::: "memory"); \
    } while (0)

    ISSUE(0, 0);

    for (int ch = 0; ch < nch; ch++) {
        if (ch + 1 < nch) {
            ISSUE(ch + 1, (ch + 1) & 1);
            asm volatile("cp.async.wait_group 1;" ::: "memory");
        } else {
            asm volatile("cp.async.wait_group 0;" ::: "memory");
        }
        __syncthreads();

        uint32_t base = sb + ((ch & 1) * GBUF) * 2;
        uint32_t tAh = base;
        uint32_t tAl = base + GTILE * 2;
        uint32_t tBh = base + 2 * GTILE * 2;
        uint32_t tBl = base + 3 * GTILE * 2;

        #pragma unroll
        for (int ks = 0; ks < 2; ks++) {
            int k0 = ks * 16;
            uint32_t ahf[4][4], alf[4][4];
            #pragma unroll
            for (int mf = 0; mf < 4; mf++) {
                uint32_t off = ((wm * 64 + mf * 16 + arow) * GSTRIDE + k0 + acol) * 2;
                ldmx4(ahf[mf], tAh + off);
                ldmx4(alf[mf], tAl + off);
            }
            uint32_t bhf[2][4], blf[2][4];
            #pragma unroll
            for (int ng = 0; ng < 2; ng++) {
                uint32_t off = ((wn * 32 + ng * 16 + brow) * GSTRIDE + k0 + bcol) * 2;
                ldmx4(bhf[ng], tBh + off);
                ldmx4(blf[ng], tBl + off);
            }
            #pragma unroll
            for (int mf = 0; mf < 4; mf++) {
                #pragma unroll
                for (int ng = 0; ng < 2; ng++) {
                    mma16816(acc[mf][ng * 2],     ahf[mf], bhf[ng][0], bhf[ng][1]);
                    mma16816(acc[mf][ng * 2 + 1], ahf[mf], bhf[ng][2], bhf[ng][3]);
                    mma16816(acc[mf][ng * 2],     ahf[mf], blf[ng][0], blf[ng][1]);
                    mma16816(acc[mf][ng * 2 + 1], ahf[mf], blf[ng][2], blf[ng][3]);
                    mma16816(acc[mf][ng * 2],     alf[mf], bhf[ng][0], bhf[ng][1]);
                    mma16816(acc[mf][ng * 2 + 1], alf[mf], bhf[ng][2], bhf[ng][3]);
                }
            }
        }
        __syncthreads();
    }

    int tr = lane >> 2, tc = (lane & 3) * 2;
    #pragma unroll
    for (int mf = 0; mf < 4; mf++) {
        #pragma unroll
        for (int half = 0; half < 2; half++) {
            long row = m0 + wm * 64 + mf * 16 + tr + half * 8;
            #pragma unroll
            for (int nf = 0; nf < 4; nf++) {
                int col = n0 + wn * 32 + nf * 8 + tc;
                float v0 = acc[mf][nf][half * 2 + 0];
                float v1 = acc[mf][nf][half * 2 + 1];
                if (bias) { v0 += bias[col]; v1 += bias[col + 1]; }
                if (Cin) {
                    float2 ci = *(const float2*)(Cin + row * (long)N + col);
                    v0 += ci.x; v1 += ci.y;
                }
                if (relu) { v0 = fmaxf(v0, 0.f); v1 = fmaxf(v1, 0.f); }
                if (C) *(float2*)(C + row * (long)N + col) = make_float2(v0, v1);
                if (Oh) {
                    __nv_bfloat16 h0, l0, h1, l1;
                    split2(v0, h0, l0); split2(v1, h1, l1);
                    __nv_bfloat16 hp[2] = {h0, h1}, lp[2] = {l0, l1};
                    *(uint32_t*)(Oh + row * (long)N + col) = *(uint32_t*)hp;
                    *(uint32_t*)(Ol + row * (long)N + col) = *(uint32_t*)lp;
                }
            }
        }
    }
}

// ---------------- small-N fp32 GEMM (head, N=65) ----------------
__global__ void gemm_k(const float* __restrict__ A, const float* __restrict__ Bw,
                       const float* __restrict__ bias, float* __restrict__ C,
                       int N, int K) {
    __shared__ float As[8][128];
    __shared__ float Bs[8][128];
    int tid = threadIdx.x;
    int m0 = blockIdx.y * 128, n0 = blockIdx.x * 128;
    int arow = tid >> 1, ac4 = (tid & 1) * 4;
    int brow = tid >> 5, bcol = (tid & 31) * 4;
    int ty = tid >> 4, tx = tid & 15;

    float acc[8][8];
    #pragma unroll
    for (int i = 0; i < 8; i++)
        #pragma unroll
        for (int j = 0; j < 8; j++) acc[i][j] = 0.f;

    const float* Aptr = A + (long)(m0 + arow) * K + ac4;

    for (int kt = 0; kt < K; kt += 8) {
        float4 av = *(const float4*)(Aptr + kt);
        As[ac4 + 0][arow] = av.x; As[ac4 + 1][arow] = av.y;
        As[ac4 + 2][arow] = av.z; As[ac4 + 3][arow] = av.w;

        int col = n0 + bcol;
        const float* bp = Bw + (long)(kt + brow) * N;
        float4 bv;
        bv.x = (col + 0 < N) ? bp[col + 0] : 0.f;
        bv.y = (col + 1 < N) ? bp[col + 1] : 0.f;
        bv.z = (col + 2 < N) ? bp[col + 2] : 0.f;
        bv.w = (col + 3 < N) ? bp[col + 3] : 0.f;
        *(float4*)&Bs[brow][bcol] = bv;
        __syncthreads();

        #pragma unroll
        for (int kk = 0; kk < 8; kk++) {
            float a[8], bb[8];
            *(float4*)&a[0]  = *(const float4*)&As[kk][ty * 8];
            *(float4*)&a[4]  = *(const float4*)&As[kk][ty * 8 + 4];
            *(float4*)&bb[0] = *(const float4*)&Bs[kk][tx * 8];
            *(float4*)&bb[4] = *(const float4*)&Bs[kk][tx * 8 + 4];
            #pragma unroll
            for (int i = 0; i < 8; i++)
                #pragma unroll
                for (int j = 0; j < 8; j++) acc[i][j] += a[i] * bb[j];
        }
        __syncthreads();
    }

    #pragma unroll
    for (int i = 0; i < 8; i++) {
        long row = m0 + ty * 8 + i;
        float* crow = C + row * (long)N;
        #pragma unroll
        for (int j = 0; j < 8; j++) {
            int col = n0 + tx * 8 + j;
            if (col < N) crow[col] = acc[i][j] + (bias ? bias[col] : 0.f);
        }
    }
}

// ---------------- tensor-core flash attention ----------------
// grid (bh, qblock). 8 warps; each warp owns 16 q-rows, iterates 128-key chunks.
// S = 3-pass split QK^T (f32 acc); P bf16; O += P*Vh + P*Vl.
// ASTRIDE = 72 (64 data + 8 pad): full HS=64 rows fit; 8-row ldmatrix phases
// 4r mod 32 words -> conflict-free.
#define ASTRIDE 72
#define ATILE   (128*ASTRIDE)   // elems per smem tile
__global__ void __launch_bounds__(256)
fattn_k(const float* __restrict__ qkv,
        __nv_bfloat16* __restrict__ oh, __nv_bfloat16* __restrict__ ol) {
    extern __shared__ __align__(16) char sma[];
    __nv_bfloat16* Qh = (__nv_bfloat16*)sma;
    __nv_bfloat16* Ql = Qh + ATILE;
    __nv_bfloat16* Kh = Qh + 2 * ATILE;
    __nv_bfloat16* Kl = Qh + 3 * ATILE;
    __nv_bfloat16* Vh = Qh + 4 * ATILE;
    __nv_bfloat16* Vl = Qh + 5 * ATILE;
    uint32_t sb = s2u(sma);

    int bh = blockIdx.x;
    int b = bh / H_, h = bh % H_;
    int qb = blockIdx.y;
    int tid = threadIdx.x, wid = tid >> 5, lane = tid & 31;
    const float* base = qkv + (long)b * T_ * 3 * D_;
    const float scale = 0.05103103630798288f;  // 384^-0.5

    // loader: 128 rows x 64 f32 at (trow0, coloff) -> split into Sh/Sl
    #define LOADSPLIT(trow0, coloff, Sh, Sl) do { \
        _Pragma("unroll") \
        for (int it = 0; it < 8; it++) { \
            int id = tid + it * 256; \
            int r = id >> 4, c4 = id & 15; \
            float4 v = *(const float4*)(base + (long)((trow0) + r) * (3 * D_) + (coloff) + c4 * 4); \
            __nv_bfloat16 hp[4], lp[4]; \
            split2(v.x, hp[0], lp[0]); split2(v.y, hp[1], lp[1]); \
            split2(v.z, hp[2], lp[2]); split2(v.w, hp[3], lp[3]); \
            *(uint2*)((Sh) + r * ASTRIDE + c4 * 4) = *(uint2*)hp; \
            *(uint2*)((Sl) + r * ASTRIDE + c4 * 4) = *(uint2*)lp; \
        } \
    } while (0)

    LOADSPLIT(qb * 128, h * HS_, Qh, Ql);
    LOADSPLIT(0, D_ + h * HS_, Kh, Kl);
    LOADSPLIT(0, 2 * D_ + h * HS_, Vh, Vl);
    __syncthreads();

    int sel  = lane >> 3;
    int arow = (lane & 7) + ((sel & 1) << 3);
    int acol = (sel >> 1) << 3;
    int brow = (lane & 7) + ((sel >> 1) << 3);
    int bcol = (sel & 1) << 3;
    int vrow = (lane & 7) + (((lane >> 3) & 1) << 3);
    int vcol = ((lane >> 4) & 1) << 3;

    uint32_t qfh[4][4], qfl[4][4];
    #pragma unroll
    for (int ks = 0; ks < 4; ks++) {
        uint32_t off = ((wid * 16 + arow) * ASTRIDE + ks * 16 + acol) * 2;
        ldmx4(qfh[ks], sb + 0 * ATILE * 2 + off);
        ldmx4(qfl[ks], sb + 1 * ATILE * 2 + off);
    }

    float So[8][4];
    #pragma unroll
    for (int a = 0; a < 8; a++)
        #pragma unroll
        for (int j = 0; j < 4; j++) So[a][j] = 0.f;
    float mrow0 = -1e30f, mrow1 = -1e30f, lrow0 = 0.f, lrow1 = 0.f;

    const int rg0 = qb * 128 + wid * 16 + (lane >> 2);   // global q row (c0/c1)
    const int ccol = (lane & 3) * 2;

    for (int ch = 0; ch <= qb; ch++) {
        if (ch) {
            __syncthreads();
            LOADSPLIT(ch * 128, D_ + h * HS_, Kh, Kl);
            LOADSPLIT(ch * 128, 2 * D_ + h * HS_, Vh, Vl);
            __syncthreads();
        }
        // ---- S = Q K^T (3 passes) ----
        float sa[16][4];
        #pragma unroll
        for (int ni = 0; ni < 16; ni++)
            #pragma unroll
            for (int j = 0; j < 4; j++) sa[ni][j] = 0.f;
        #pragma unroll
        for (int ks = 0; ks < 4; ks++) {
            #pragma unroll
            for (int ng = 0; ng < 8; ng++) {
                uint32_t off = ((ng * 16 + brow) * ASTRIDE + ks * 16 + bcol) * 2;
                uint32_t kh4[4], kl4[4];
                ldmx4(kh4, sb + 2 * ATILE * 2 + off);
                ldmx4(kl4, sb + 3 * ATILE * 2 + off);
                mma16816(sa[ng * 2],     qfh[ks], kh4[0], kh4[1]);
                mma16816(sa[ng * 2 + 1], qfh[ks], kh4[2], kh4[3]);
                mma16816(sa[ng * 2],     qfh[ks], kl4[0], kl4[1]);
                mma16816(sa[ng * 2 + 1], qfh[ks], kl4[2], kl4[3]);
                mma16816(sa[ng * 2],     qfl[ks], kh4[0], kh4[1]);
                mma16816(sa[ng * 2 + 1], qfl[ks], kh4[2], kh4[3]);
            }
        }
        // ---- scale + causal mask ----
        bool diag = (ch == qb);
        #pragma unroll
        for (int ni = 0; ni < 16; ni++) {
            #pragma unroll
            for (int j = 0; j < 4; j++) {
                float s = sa[ni][j] * scale;
                if (diag) {
                    int key = ch * 128 + ni * 8 + ccol + (j & 1);
                    int qr  = rg0 + ((j >> 1) << 3);
                    if (key > qr) s = -1e30f;
                }
                sa[ni][j] = s;
            }
        }
        // ---- online softmax ----
        float mx0 = -1e30f, mx1 = -1e30f;
        #pragma unroll
        for (int ni = 0; ni < 16; ni++) {
            mx0 = fmaxf(mx0, fmaxf(sa[ni][0], sa[ni][1]));
            mx1 = fmaxf(mx1, fmaxf(sa[ni][2], sa[ni][3]));
        }
        mx0 = fmaxf(mx0, __shfl_xor_sync(0xffffffffu, mx0, 1));
        mx0 = fmaxf(mx0, __shfl_xor_sync(0xffffffffu, mx0, 2));
        mx1 = fmaxf(mx1, __shfl_xor_sync(0xffffffffu, mx1, 1));
        mx1 = fmaxf(mx1, __shfl_xor_sync(0xffffffffu, mx1, 2));
        float mn0 = fmaxf(mrow0, mx0), mn1 = fmaxf(mrow1, mx1);
        float c0 = __expf(mrow0 - mn0), c1 = __expf(mrow1 - mn1);
        mrow0 = mn0; mrow1 = mn1;
        float s0 = 0.f, s1 = 0.f;
        #pragma unroll
        for (int ni = 0; ni < 16; ni++) {
            sa[ni][0] = __expf(sa[ni][0] - mn0);
            sa[ni][1] = __expf(sa[ni][1] - mn0);
            sa[ni][2] = __expf(sa[ni][2] - mn1);
            sa[ni][3] = __expf(sa[ni][3] - mn1);
            s0 += sa[ni][0] + sa[ni][1];
            s1 += sa[ni][2] + sa[ni][3];
        }
        s0 += __shfl_xor_sync(0xffffffffu, s0, 1);
        s0 += __shfl_xor_sync(0xffffffffu, s0, 2);
        s1 += __shfl_xor_sync(0xffffffffu, s1, 1);
        s1 += __shfl_xor_sync(0xffffffffu, s1, 2);
        lrow0 = lrow0 * c0 + s0;
        lrow1 = lrow1 * c1 + s1;
        #pragma unroll
        for (int a = 0; a < 8; a++) {
            So[a][0] *= c0; So[a][1] *= c0;
            So[a][2] *= c1; So[a][3] *= c1;
        }
        // ---- O += P * V (2 passes) ----
        #pragma unroll
        for (int ks = 0; ks < 8; ks++) {
            uint32_t pf[4];
            pf[0] = pk2f(sa[2 * ks][0],     sa[2 * ks][1]);
            pf[1] = pk2f(sa[2 * ks][2],     sa[2 * ks][3]);
            pf[2] = pk2f(sa[2 * ks + 1][0], sa[2 * ks + 1][1]);
            pf[3] = pk2f(sa[2 * ks + 1][2], sa[2 * ks + 1][3]);
            #pragma unroll
            for (int np = 0; np < 4; np++) {
                uint32_t voff = ((ks * 16 + vrow) * ASTRIDE + np * 16 + vcol) * 2;
                uint32_t vh4[4], vl4[4];
                ldmx4t(vh4, sb + 4 * ATILE * 2 + voff);
                ldmx4t(vl4, sb + 5 * ATILE * 2 + voff);
                mma16816(So[np * 2],     pf, vh4[0], vh4[1]);
                mma16816(So[np * 2 + 1], pf, vh4[2], vh4[3]);
                mma16816(So[np * 2],     pf, vl4[0], vl4[1]);
                mma16816(So[np * 2 + 1], pf, vl4[2], vl4[3]);
            }
        }
    }

    // ---- write output (split bf16) ----
    float rl0 = 1.f / lrow0, rl1 = 1.f / lrow1;
    #pragma unroll
    for (int a = 0; a < 8; a++) {
        int col = h * HS_ + a * 8 + ccol;
        long row0 = (long)b * T_ + rg0;
        long row1 = row0 + 8;
        float v0 = So[a][0] * rl0, v1 = So[a][1] * rl0;
        float v2 = So[a][2] * rl1, v3 = So[a][3] * rl1;
        __nv_bfloat16 h0, l0, h1, l1;
        split2(v0, h0, l0); split2(v1, h1, l1);
        __nv_bfloat16 hp[2] = {h0, h1}, lp[2] = {l0, l1};
        *(uint32_t*)(oh + row0 * D_ + col) = *(uint32_t*)hp;
        *(uint32_t*)(ol + row0 * D_ + col) = *(uint32_t*)lp;
        split2(v2, h0, l0); split2(v3, h1, l1);
        __nv_bfloat16 hp2[2] = {h0, h1}, lp2[2] = {l0, l1};
        *(uint32_t*)(oh + row1 * D_ + col) = *(uint32_t*)hp2;
        *(uint32_t*)(ol + row1 * D_ + col) = *(uint32_t*)lp2;
    }
}

// ---------------- loss ----------------
__global__ void loss_k(const float* __restrict__ logits, const int* __restrict__ targets,
                       float* __restrict__ part) {
    int gwarp = (blockIdx.x * blockDim.x + threadIdx.x) >> 5;
    int lane = threadIdx.x & 31;
    const float* lr = logits + (long)gwarp * V_;
    float mx = -1e30f;
    for (int c = lane; c < V_; c += 32) mx = fmaxf(mx, lr[c]);
    #pragma unroll
    for (int o = 16; o; o >>= 1) mx = fmaxf(mx, __shfl_xor_sync(0xffffffffu, mx, o));
    float se = 0.f;
    for (int c = lane; c < V_; c += 32) se += expf(lr[c] - mx);
    #pragma unroll
    for (int o = 16; o; o >>= 1) se += __shfl_xor_sync(0xffffffffu, se, o);
    float li = (mx + logf(se)) - lr[targets[gwarp]];
    __shared__ float ws[8];
    if (lane == 0) ws[threadIdx.x >> 5] = li;
    __syncthreads();
    if (threadIdx.x == 0) {
        float s = 0.f;
        #pragma unroll
        for (int i = 0; i < 8; i++) s += ws[i];
        part[blockIdx.x] = s;
    }
}

__global__ void finalize_k(float* out, long out_size, const float* __restrict__ part) {
    float v = 0.f;
    for (int i = threadIdx.x; i < 2048; i += 256) v += part[i];
    #pragma unroll
    for (int o = 16; o; o >>= 1) v += __shfl_xor_sync(0xffffffffu, v, o);
    __shared__ float sm[8];
    if ((threadIdx.x & 31) == 0) sm[threadIdx.x >> 5] = v;
    __syncthreads();
    if (threadIdx.x == 0) {
        float s = 0.f;
        #pragma unroll
        for (int i = 0; i < 8; i++) s += sm[i];
        float loss = s / (float)M_;
        const long btv = (long)M_ * V_;
        if (out_size > btv)       out[btv] = loss;
        else if (out_size == 1)   out[0]   = loss;
    }
}

// ---------------- driver ----------------
extern "C" void kernel_launch(void* const* d_in, const int* in_sizes, int n_in,
                              void* d_out, int out_size) {
    const int*   idx     = (const int*)d_in[0];
    const int*   targets = (const int*)d_in[1];
    const float* tok     = (const float*)d_in[2];
    const float* pos     = (const float*)d_in[3];
    const float* Wq      = (const float*)d_in[4];
    const float* Wk      = (const float*)d_in[5];
    const float* Wv      = (const float*)d_in[6];
    const float* Wproj   = (const float*)d_in[7];
    const float* bproj   = (const float*)d_in[8];
    const float* W1      = (const float*)d_in[9];
    const float* b1      = (const float*)d_in[10];
    const float* W2      = (const float*)d_in[11];
    const float* b2      = (const float*)d_in[12];
    const float* ln1g    = (const float*)d_in[13];
    const float* ln1b    = (const float*)d_in[14];
    const float* lnfg    = (const float*)d_in[15];
    const float* lnfb    = (const float*)d_in[16];
    const float* Whead   = (const float*)d_in[17];
    const float* bhead   = (const float*)d_in[18];
    float* out = (float*)d_out;

    float *x, *y, *qkv, *lgts, *part;
    __nv_bfloat16 *yh, *yl, *oh, *ol, *h1h, *h1l;
    __nv_bfloat16 *wqh, *wql, *wph, *wpl, *w1h, *w1l, *w2h, *w2l;
    cudaGetSymbolAddress((void**)&x,    g_x);
    cudaGetSymbolAddress((void**)&y,    g_y);
    cudaGetSymbolAddress((void**)&qkv,  g_qkv);
    cudaGetSymbolAddress((void**)&lgts, g_logits);
    cudaGetSymbolAddress((void**)&part, g_losspart);
    cudaGetSymbolAddress((void**)&yh,   g_yh);
    cudaGetSymbolAddress((void**)&yl,   g_yl);
    cudaGetSymbolAddress((void**)&oh,   g_oh);
    cudaGetSymbolAddress((void**)&ol,   g_ol);
    cudaGetSymbolAddress((void**)&h1h,  g_h1h);
    cudaGetSymbolAddress((void**)&h1l,  g_h1l);
    cudaGetSymbolAddress((void**)&wqh,  g_wqkvh);
    cudaGetSymbolAddress((void**)&wql,  g_wqkvl);
    cudaGetSymbolAddress((void**)&wph,  g_wprojh);
    cudaGetSymbolAddress((void**)&wpl,  g_wprojl);
    cudaGetSymbolAddress((void**)&w1h,  g_w1h);
    cudaGetSymbolAddress((void**)&w1l,  g_w1l);
    cudaGetSymbolAddress((void**)&w2h,  g_w2h);
    cudaGetSymbolAddress((void**)&w2l,  g_w2l);

    const int attn_smem = 6 * ATILE * 2;          // 110592 B
    cudaFuncSetAttribute(fattn_k, cudaFuncAttributeMaxDynamicSharedMemorySize, attn_smem);
    const int gsmem = 2 * GBUF * 2;               // 81920 B
    cudaFuncSetAttribute(gemm_bf16_k, cudaFuncAttributeMaxDynamicSharedMemorySize, gsmem);

    const long btv = (long)M_ * V_;
    float* logits = ((long)out_size >= btv) ? out : lgts;

    {
        long tq = (long)L_ * 3 * D_ * D_;
        convqkv_k<<<(int)((tq + 255) / 256), 256>>>(Wq, Wk, Wv, wqh, wql);
        long tp = (long)L_ * D_ * D_;
        convt_k<<<(int)((tp + 255) / 256), 256>>>(Wproj, wph, wpl, D_, D_);
        long t1 = (long)L_ * FF_ * D_;
        convt_k<<<(int)((t1 + 255) / 256), 256>>>(W1, w1h, w1l, D_, FF_);
        long t2 = (long)L_ * D_ * FF_;
        convt_k<<<(int)((t2 + 255) / 256), 256>>>(W2, w2h, w2l, FF_, D_);
    }
    embed_k<<<(M_ * D_ + 255) / 256, 256>>>(idx, tok, pos, x);

    for (int l = 0; l < L_; l++) {
        ln_k<<<M_, 128>>>(x, (float*)0, yh, yl, ln1g + (long)l * D_, ln1b + (long)l * D_);
        { dim3 g(9, 128);
          gemm_bf16_k<<<g, 256, gsmem>>>(yh, yl,
              wqh + (long)l * 3 * D_ * D_, wql + (long)l * 3 * D_ * D_,
              (const float*)0, (const float*)0, qkv,
              (__nv_bfloat16*)0, (__nv_bfloat16*)0, 3 * D_, D_, 0); }
        { dim3 ga(B_ * H_, 2);
          fattn_k<<<ga, 256, attn_smem>>>(qkv, oh, ol); }
        { dim3 g(3, 128);
          gemm_bf16_k<<<g, 256, gsmem>>>(oh, ol,
              wph + (long)l * D_ * D_, wpl + (long)l * D_ * D_,
              bproj + (long)l * D_, x, x,
              (__nv_bfloat16*)0, (__nv_bfloat16*)0, D_, D_, 0); }
        ln_k<<<M_, 128>>>(x, (float*)0, yh, yl, ln1g + (long)l * D_, ln1b + (long)l * D_);
        { dim3 g(12, 128);
          gemm_bf16_k<<<g, 256, gsmem>>>(yh, yl,
              w1h + (long)l * FF_ * D_, w1l + (long)l * FF_ * D_,
              b1 + (long)l * FF_, (const float*)0, (float*)0,
              h1h, h1l, FF_, D_, 1); }
        { dim3 g(3, 128);
          gemm_bf16_k<<<g, 256, gsmem>>>(h1h, h1l,
              w2h + (long)l * D_ * FF_, w2l + (long)l * D_ * FF_,
              b2 + (long)l * D_, x, x,
              (__nv_bfloat16*)0, (__nv_bfloat16*)0, D_, FF_, 0); }
    }

    ln_k<<<M_, 128>>>(x, y, (__nv_bfloat16*)0, (__nv_bfloat16*)0, lnfg, lnfb);
    { dim3 g(1, 128); gemm_k<<<g, 256>>>(y, Whead, bhead, logits, V_, D_); }
    loss_k<<<2048, 256>>>(logits, targets, part);
    finalize_k<<<1, 256>>>(out, (long)out_size, part);
}